// round 4
// baseline (speedup 1.0000x reference)
#include <cuda_runtime.h>
#include <stdint.h>

#define K_CODES 1024
#define D_DIM   256
#define N_TOK   32768
#define S_PER_B 4096
#define Q_ELEMS (8u*256u*4096u)   /* 8388608 */

#define BM 128
#define BN 128
#define BK 16

// ---------------- device scratch (no allocations allowed) ----------------
__device__ float g_eTm2[D_DIM * K_CODES];   // -2 * embed^T, [D][K]
__device__ float g_e2[K_CODES];             // |e_k|^2
__device__ int   g_idx[N_TOK];
__device__ float g_batch_cs[K_CODES];
__device__ float g_dw[K_CODES * D_DIM];
__device__ float g_partials[64 * 128];
__device__ float g_cs[K_CODES];

// ---------------- prep: e2 + scaled transpose ----------------
__global__ void k_prep(const float* __restrict__ embed) {
    int k = blockIdx.x;
    int d = threadIdx.x;
    float v = embed[k * D_DIM + d];
    g_eTm2[d * K_CODES + k] = -2.0f * v;
    float s = v * v;
    #pragma unroll
    for (int o = 16; o; o >>= 1) s += __shfl_down_sync(0xffffffffu, s, o);
    __shared__ float ws[8];
    if ((d & 31) == 0) ws[d >> 5] = s;
    __syncthreads();
    if (d == 0) {
        float t = 0.f;
        #pragma unroll
        for (int i = 0; i < 8; i++) t += ws[i];
        g_e2[k] = t;
    }
}

// ---------------- main: fp32x2 packed GEMM + argmin epilogue ----------------
// score(n,k) = sum_d x[n,d] * (-2 e[k,d])  + |e_k|^2   (== d2 - |x|^2)
// Accumulators packed along the j (codebook) axis as f32x2 pairs; B pairs come
// free from the 16B smem loads; A scalar is broadcast-packed via mov.b64.
// Per-element fma order is identical to the scalar version (bitwise same).
__global__ void __launch_bounds__(256, 2) k_argmin(
    const float* __restrict__ x, float* __restrict__ idxf_out)
{
    __shared__ __align__(16) float smem[4 * BK * BM];   // 32 KB
    float* sAbuf[2] = { smem,        smem + 2048 };
    float* sBbuf[2] = { smem + 4096, smem + 6144 };

    const int tid = threadIdx.x;
    const int tx  = tid & 15;
    const int ty  = tid >> 4;
    const int m0  = blockIdx.x * BM;
    const int b   = m0 >> 12;
    const int s0  = m0 & 4095;
    const float* Abase = x + (size_t)b * (D_DIM * S_PER_B) + s0;

    const int lr = tid >> 5;          // loader row 0..7
    const int lc = (tid & 31) << 2;   // loader col 0..124

    float minv[8];
    int   mini[8];
    #pragma unroll
    for (int i = 0; i < 8; i++) { minv[i] = 3.4e38f; mini[i] = 0; }

    for (int k0 = 0; k0 < K_CODES; k0 += BN) {
        // acc2[i][jp] = (acc[i][2jp], acc[i][2jp+1]) packed f32x2
        unsigned long long acc2[8][4];
        #pragma unroll
        for (int i = 0; i < 8; i++)
            #pragma unroll
            for (int j = 0; j < 4; j++) acc2[i][j] = 0ull;

        // prologue: load d-tile 0
        const float* ap = Abase + lr * S_PER_B + lc;
        const float* bp = g_eTm2 + lr * K_CODES + k0 + lc;
        float4 ra0 = *(const float4*)(ap);
        float4 ra1 = *(const float4*)(ap + 8 * S_PER_B);
        float4 rb0 = *(const float4*)(bp);
        float4 rb1 = *(const float4*)(bp + 8 * K_CODES);
        *(float4*)(sAbuf[0] + lr * BM + lc)        = ra0;
        *(float4*)(sAbuf[0] + (lr + 8) * BM + lc)  = ra1;
        *(float4*)(sBbuf[0] + lr * BN + lc)        = rb0;
        *(float4*)(sBbuf[0] + (lr + 8) * BN + lc)  = rb1;
        __syncthreads();

        int cur = 0;
        #pragma unroll 1
        for (int dt = 0; dt < 16; dt++) {
            if (dt < 15) {
                const float* ap2 = Abase + ((dt + 1) * BK + lr) * S_PER_B + lc;
                const float* bp2 = g_eTm2 + ((dt + 1) * BK + lr) * K_CODES + k0 + lc;
                ra0 = *(const float4*)(ap2);
                ra1 = *(const float4*)(ap2 + 8 * S_PER_B);
                rb0 = *(const float4*)(bp2);
                rb1 = *(const float4*)(bp2 + 8 * K_CODES);
            }
            const float* cA = sAbuf[cur];
            const float* cB = sBbuf[cur];
            #pragma unroll
            for (int kk = 0; kk < BK; kk++) {
                float4 A0 = *(const float4*)(cA + kk * BM + ty * 8);
                float4 A1 = *(const float4*)(cA + kk * BM + ty * 8 + 4);
                // B pairs directly as packed f32x2 (16B-aligned smem)
                ulonglong2 Bp0 = *(const ulonglong2*)(cB + kk * BN + tx * 8);
                ulonglong2 Bp1 = *(const ulonglong2*)(cB + kk * BN + tx * 8 + 4);
                unsigned long long b2[4] = {Bp0.x, Bp0.y, Bp1.x, Bp1.y};
                float a[8] = {A0.x, A0.y, A0.z, A0.w, A1.x, A1.y, A1.z, A1.w};
                #pragma unroll
                for (int i = 0; i < 8; i++) {
                    unsigned long long a2;
                    asm("mov.b64 %0, {%1, %1};" : "=l"(a2) : "f"(a[i]));
                    #pragma unroll
                    for (int j = 0; j < 4; j++)
                        asm("fma.rn.f32x2 %0, %1, %2, %0;"
                            : "+l"(acc2[i][j]) : "l"(a2), "l"(b2[j]));
                }
            }
            if (dt < 15) {
                int nxt = cur ^ 1;
                *(float4*)(sAbuf[nxt] + lr * BM + lc)       = ra0;
                *(float4*)(sAbuf[nxt] + (lr + 8) * BM + lc) = ra1;
                *(float4*)(sBbuf[nxt] + lr * BN + lc)       = rb0;
                *(float4*)(sBbuf[nxt] + (lr + 8) * BN + lc) = rb1;
                __syncthreads();
                cur = nxt;
            }
        }

        // epilogue: add |e|^2, update running argmin
        float4 E0 = *(const float4*)(g_e2 + k0 + tx * 8);
        float4 E1 = *(const float4*)(g_e2 + k0 + tx * 8 + 4);
        float ev[8] = {E0.x, E0.y, E0.z, E0.w, E1.x, E1.y, E1.z, E1.w};
        #pragma unroll
        for (int i = 0; i < 8; i++) {
            #pragma unroll
            for (int jp = 0; jp < 4; jp++) {
                unsigned lo, hi;
                asm("mov.b64 {%0, %1}, %2;" : "=r"(lo), "=r"(hi) : "l"(acc2[i][jp]));
                float v0 = __uint_as_float(lo) + ev[2 * jp];
                float v1 = __uint_as_float(hi) + ev[2 * jp + 1];
                int j0 = k0 + tx * 8 + 2 * jp;
                if (v0 < minv[i]) { minv[i] = v0; mini[i] = j0; }
                if (v1 < minv[i]) { minv[i] = v1; mini[i] = j0 + 1; }
            }
        }
        __syncthreads();   // before next k-tile reuses smem buffers
    }

    // cross-thread reduction: 16 threads (tx) share each of 128 rows
    float* redv = smem;                    // [128][16]
    int*   redi = (int*)(smem + 2048);     // [128][16]
    #pragma unroll
    for (int i = 0; i < 8; i++) {
        int row = ty * 8 + i;
        redv[row * 16 + tx] = minv[i];
        redi[row * 16 + tx] = mini[i];
    }
    __syncthreads();
    if (tid < BM) {
        float bv = redv[tid * 16];
        int   bi = redi[tid * 16];
        #pragma unroll
        for (int q = 1; q < 16; q++) {
            float v = redv[tid * 16 + q];
            int  ii = redi[tid * 16 + q];
            if (v < bv || (v == bv && ii < bi)) { bv = v; bi = ii; }
        }
        int n = m0 + tid;
        g_idx[n] = bi;
        idxf_out[n] = (float)bi;
        atomicAdd(&g_batch_cs[bi], 1.0f);
    }
}

// ---------------- fused quantized write + loss partials + dw scatter ----------------
__global__ void k_quant_dw(const float* __restrict__ x,
                           const float* __restrict__ embed,
                           float* __restrict__ qout)
{
    int d0 = blockIdx.x << 2;
    int n  = (blockIdx.y << 8) + threadIdx.x;
    int b = n >> 12, s = n & 4095;
    size_t base = (size_t)b * (D_DIM * S_PER_B) + s;
    int k = g_idx[n];
    float4 q = *(const float4*)(embed + k * D_DIM + d0);

    float x0 = x[base + (size_t)(d0 + 0) * S_PER_B];
    float x1 = x[base + (size_t)(d0 + 1) * S_PER_B];
    float x2 = x[base + (size_t)(d0 + 2) * S_PER_B];
    float x3 = x[base + (size_t)(d0 + 3) * S_PER_B];

    float t0 = q.x - x0, t1 = q.y - x1, t2 = q.z - x2, t3 = q.w - x3;
    qout[base + (size_t)(d0 + 0) * S_PER_B] = x0 + t0;
    qout[base + (size_t)(d0 + 1) * S_PER_B] = x1 + t1;
    qout[base + (size_t)(d0 + 2) * S_PER_B] = x2 + t2;
    qout[base + (size_t)(d0 + 3) * S_PER_B] = x3 + t3;
    float ls = t0 * t0 + t1 * t1 + t2 * t2 + t3 * t3;

    // dw scatter-add (same x values, saves a full second read of x)
    float* dst = g_dw + k * D_DIM + d0;
    asm volatile("red.global.add.v4.f32 [%0], {%1,%2,%3,%4};"
                 :: "l"(dst), "f"(x0), "f"(x1), "f"(x2), "f"(x3) : "memory");

    #pragma unroll
    for (int o = 16; o; o >>= 1) ls += __shfl_down_sync(0xffffffffu, ls, o);
    __shared__ float ws[8];
    int tid = threadIdx.x;
    if ((tid & 31) == 0) ws[tid >> 5] = ls;
    __syncthreads();
    if (tid == 0) {
        float sum = 0.f;
        #pragma unroll
        for (int i = 0; i < 8; i++) sum += ws[i];
        g_partials[blockIdx.y * 64 + blockIdx.x] = sum;
    }
}

// ---------------- finalize: loss, cluster-size normalization ----------------
__global__ void k_final(const float* __restrict__ cluster_size,
                        float* __restrict__ loss_out)
{
    __shared__ float sb[1024];
    int t = threadIdx.x;
    float s = 0.f;
    for (int i = t; i < 64 * 128; i += 1024) s += g_partials[i];
    sb[t] = s; __syncthreads();
    for (int o = 512; o; o >>= 1) { if (t < o) sb[t] += sb[t + o]; __syncthreads(); }
    if (t == 0) loss_out[0] = 0.25f * sb[0] / (float)Q_ELEMS;
    __syncthreads();

    float ncs = cluster_size[t] * 0.99f + 0.01f * g_batch_cs[t];
    sb[t] = ncs; __syncthreads();
    for (int o = 512; o; o >>= 1) { if (t < o) sb[t] += sb[t + o]; __syncthreads(); }
    float nsum = sb[0];
    g_cs[t] = nsum * (ncs + 1e-5f) / (nsum + 1024.0f * 1e-5f);
}

// ---------------- new embed ----------------
__global__ void k_newembed(const float* __restrict__ embed_avg,
                           float* __restrict__ out)
{
    int k = blockIdx.x, d = threadIdx.x;
    int o = k * D_DIM + d;
    out[o] = (embed_avg[o] * 0.99f + 0.01f * g_dw[o]) / g_cs[k];
}

// ---------------- launch ----------------
extern "C" void kernel_launch(void* const* d_in, const int* in_sizes, int n_in,
                              void* d_out, int out_size)
{
    const float* x          = (const float*)d_in[0];
    const float* embed      = (const float*)d_in[1];
    const float* embed_avg  = (const float*)d_in[2];
    const float* cluster    = (const float*)d_in[3];

    float* out     = (float*)d_out;
    float* out_q   = out + 1;                 // quantized [B,C,T,H,W]
    float* out_idx = out_q + Q_ELEMS;         // idx as float [B,T,H,W]
    float* out_e   = out_idx + N_TOK;         // new_embed [K,D]

    void *p_dw, *p_bc;
    cudaGetSymbolAddress(&p_dw, g_dw);
    cudaGetSymbolAddress(&p_bc, g_batch_cs);
    cudaMemsetAsync(p_dw, 0, sizeof(float) * K_CODES * D_DIM, 0);
    cudaMemsetAsync(p_bc, 0, sizeof(float) * K_CODES, 0);

    k_prep<<<K_CODES, D_DIM>>>(embed);
    k_argmin<<<N_TOK / BM, 256>>>(x, out_idx);
    dim3 g(64, 128);
    k_quant_dw<<<g, 256>>>(x, embed, out_q);
    k_final<<<1, 1024>>>(cluster, out);
    k_newembed<<<K_CODES, D_DIM>>>(embed_avg, out_e);
}

// round 6
// speedup vs baseline: 1.7968x; 1.7968x over previous
#include <cuda_runtime.h>
#include <cuda_bf16.h>
#include <stdint.h>

typedef unsigned u32; typedef unsigned long long u64;

#define K_CODES 1024
#define D_DIM   256
#define N_TOK   32768
#define Q_ELEMS (8u*256u*4096u)
#define TAU     0.02f

#define XPITCH  264        /* x smem row pitch in bf16 elements (528 B)   */
#define BPITCH  144        /* e tile row pitch in bytes (128 data + 16)   */
#define SM_XH   0
#define SM_XL   67584
#define SM_B    135168
#define SM_BT   18432      /* one 128-code x 64-d bf16 tile               */
#define SM_TOTAL 208896

// ---------------- device scratch ----------------
__device__ __align__(16) __nv_bfloat16 g_Ebf[2][K_CODES][D_DIM];  // hi/lo of -2*embed
__device__ float g_e2[K_CODES];
__device__ int   g_idx[N_TOK];
__device__ float g_batch_cs[K_CODES];
__device__ float g_dw[K_CODES * D_DIM];
__device__ float g_partials[64 * 128];
__device__ float g_cs[K_CODES];
__device__ int   g_flag_cnt;
__device__ int   g_flag_tok[N_TOK];

// ---------------- helpers ----------------
__device__ __forceinline__ u32 smem_u32(const void* p) {
    u32 a; asm("{ .reg .u64 t; cvta.to.shared.u64 t, %1; cvt.u32.u64 %0, t; }" : "=r"(a) : "l"(p)); return a;
}
__device__ __forceinline__ u32 fkey(float v) {
    u32 u = __float_as_uint(v); return (u & 0x80000000u) ? ~u : (u | 0x80000000u);
}
__device__ __forceinline__ float fkeyinv(u32 k) {
    u32 u = (k & 0x80000000u) ? (k & 0x7FFFFFFFu) : ~k; return __uint_as_float(u);
}
__device__ __forceinline__ void cpa16(u32 dst, const void* src) {
    asm volatile("cp.async.cg.shared.global [%0], [%1], 16;" :: "r"(dst), "l"(src));
}
#define CP_COMMIT() asm volatile("cp.async.commit_group;" ::: "memory")
#define CP_WAIT1()  asm volatile("cp.async.wait_group 1;" ::: "memory")
#define CP_WAIT0()  asm volatile("cp.async.wait_group 0;" ::: "memory")

__device__ __forceinline__ void ldm4(u32& r0, u32& r1, u32& r2, u32& r3, u32 a) {
    asm volatile("ldmatrix.sync.aligned.m8n8.x4.shared.b16 {%0,%1,%2,%3}, [%4];"
                 : "=r"(r0), "=r"(r1), "=r"(r2), "=r"(r3) : "r"(a));
}
__device__ __forceinline__ void mma16816(float* c, const u32* a, const u32* b) {
    asm volatile("mma.sync.aligned.m16n8k16.row.col.f32.bf16.bf16.f32 "
                 "{%0,%1,%2,%3}, {%4,%5,%6,%7}, {%8,%9}, {%0,%1,%2,%3};"
                 : "+f"(c[0]), "+f"(c[1]), "+f"(c[2]), "+f"(c[3])
                 : "r"(a[0]), "r"(a[1]), "r"(a[2]), "r"(a[3]), "r"(b[0]), "r"(b[1]));
}

// ---------------- prep: split -2*embed into bf16 hi/lo + e2 ----------------
__global__ void k_esplit(const float* __restrict__ embed) {
    int k = blockIdx.x, d = threadIdx.x;
    float e = embed[k * D_DIM + d];
    float v = -2.0f * e;
    __nv_bfloat16 h = __float2bfloat16(v);
    g_Ebf[0][k][d] = h;
    g_Ebf[1][k][d] = __float2bfloat16(v - __bfloat162float(h));
    float s = e * e;
    #pragma unroll
    for (int o = 16; o; o >>= 1) s += __shfl_down_sync(0xffffffffu, s, o);
    __shared__ float ws[8];
    if ((d & 31) == 0) ws[d >> 5] = s;
    __syncthreads();
    if (d == 0) {
        float t = 0.f;
        #pragma unroll
        for (int i = 0; i < 8; i++) t += ws[i];
        g_e2[k] = t;
    }
}

// ---------------- main: bf16 mma.sync 3-term GEMM + argmin + margin flags ----------------
__global__ void __launch_bounds__(256, 1) k_argmin(const float* __restrict__ x) {
    extern __shared__ __align__(128) char smem[];
    u32 smb = smem_u32(smem);
    const int tid = threadIdx.x, l = tid & 31, wid = tid >> 5;
    const int wm = wid & 3, wn = wid >> 2;
    const int m0 = blockIdx.x * 128;
    const int b = m0 >> 12, s0 = m0 & 4095;

    __nv_bfloat16* xh = (__nv_bfloat16*)(smem + SM_XH);
    __nv_bfloat16* xl = (__nv_bfloat16*)(smem + SM_XL);

    // fill + split x tile: [128 tok][256 d] bf16 hi/lo
    {
        int tok = tid & 127, dh = tid >> 7;
        const float* xp = x + (size_t)b * 1048576u + s0 + tok;
        #pragma unroll 4
        for (int i = 0; i < 128; i++) {
            int d = dh + 2 * i;
            float v = xp[(size_t)d * 4096u];
            __nv_bfloat16 h = __float2bfloat16(v);
            xh[tok * XPITCH + d] = h;
            xl[tok * XPITCH + d] = __float2bfloat16(v - __bfloat162float(h));
        }
    }

    auto prefetch = [&](int step) {
        int tile = step >> 2, chunk = step & 3;
        u32 dstb = smb + SM_B + (u32)(step & 1) * (2 * SM_BT);
        #pragma unroll
        for (int op = 0; op < 2; op++) {
            const char* src0 = (const char*)&g_Ebf[op][tile * 128][0] + chunk * 128;
            u32 dst = dstb + op * SM_BT;
            #pragma unroll
            for (int i = 0; i < 4; i++) {
                int idx = tid + i * 256;
                int crow = idx >> 3, seg = idx & 7;
                cpa16(dst + crow * BPITCH + seg * 16, src0 + (size_t)crow * 512 + seg * 16);
            }
        }
        CP_COMMIT();
    };

    float acc[2][8][4];
    u64 b1[4]; u32 b2[4];
    #pragma unroll
    for (int q = 0; q < 4; q++) { b1[q] = ~0ull; b2[q] = 0xFFFFFFFFu; }
    #pragma unroll
    for (int mt = 0; mt < 2; mt++)
        #pragma unroll
        for (int nt = 0; nt < 8; nt++)
            #pragma unroll
            for (int r = 0; r < 4; r++) acc[mt][nt][r] = 0.f;

    __syncthreads();
    prefetch(0);

    const u32 aoff = (u32)((l & 7) + ((l >> 3) & 1) * 8) * 528 + ((l >> 4) & 1) * 16;
    const u32 boff = (u32)((l & 7) + ((l >> 4) & 1) * 8) * BPITCH + ((l >> 3) & 1) * 16;

    for (int step = 0; step < 32; step++) {
        int tile = step >> 2, chunk = step & 3;
        if (step < 31) { prefetch(step + 1); CP_WAIT1(); } else { CP_WAIT0(); }
        __syncthreads();
        u32 Bbase = smb + SM_B + (u32)(step & 1) * (2 * SM_BT);
        #pragma unroll
        for (int pass = 0; pass < 3; pass++) {
            u32 Ab = smb + (pass == 2 ? SM_XL : SM_XH);
            u32 Bb = Bbase + (pass == 1 ? SM_BT : 0);
            #pragma unroll
            for (int ks = 0; ks < 4; ks++) {
                u32 kbyte = (u32)chunk * 128 + ks * 32;
                u32 a[2][4];
                #pragma unroll
                for (int mt = 0; mt < 2; mt++)
                    ldm4(a[mt][0], a[mt][1], a[mt][2], a[mt][3],
                         Ab + (u32)(wm * 32 + mt * 16) * 528 + kbyte + aoff);
                u32 bb[4][4];
                #pragma unroll
                for (int ng = 0; ng < 4; ng++)
                    ldm4(bb[ng][0], bb[ng][1], bb[ng][2], bb[ng][3],
                         Bb + (u32)(wn * 64 + ng * 16) * BPITCH + ks * 32 + boff);
                #pragma unroll
                for (int mt = 0; mt < 2; mt++)
                    #pragma unroll
                    for (int ng = 0; ng < 4; ng++) {
                        mma16816(acc[mt][ng * 2],     a[mt], &bb[ng][0]);
                        mma16816(acc[mt][ng * 2 + 1], a[mt], &bb[ng][2]);
                    }
            }
        }
        if (chunk == 3) {
            // epilogue for this 128-code tile: add |e|^2, update best/2nd trackers
            float2 e2v[8];
            #pragma unroll
            for (int nt = 0; nt < 8; nt++)
                e2v[nt] = *(const float2*)(g_e2 + tile * 128 + wn * 64 + nt * 8 + 2 * (l & 3));
            #pragma unroll
            for (int mt = 0; mt < 2; mt++)
                #pragma unroll
                for (int nt = 0; nt < 8; nt++)
                    #pragma unroll
                    for (int r = 0; r < 4; r++) {
                        float v = acc[mt][nt][r] + ((r & 1) ? e2v[nt].y : e2v[nt].x);
                        u32 col = (u32)(tile * 128 + wn * 64 + nt * 8 + 2 * (l & 3) + (r & 1));
                        int tr = mt * 2 + (r >> 1);
                        u64 pk = ((u64)fkey(v) << 32) | col;
                        if (pk < b1[tr]) { b2[tr] = min(b2[tr], (u32)(b1[tr] >> 32)); b1[tr] = pk; }
                        else             { b2[tr] = min(b2[tr], (u32)(pk >> 32)); }
                        acc[mt][nt][r] = 0.f;
                    }
        }
        __syncthreads();
    }

    // merge across the 4 lanes (l&3) sharing each row
    #pragma unroll
    for (int tr = 0; tr < 4; tr++) {
        #pragma unroll
        for (int off = 1; off <= 2; off <<= 1) {
            u64 o1 = __shfl_xor_sync(0xffffffffu, b1[tr], off);
            u32 o2 = __shfl_xor_sync(0xffffffffu, b2[tr], off);
            u64 mx = (b1[tr] > o1) ? b1[tr] : o1;
            b1[tr] = (b1[tr] < o1) ? b1[tr] : o1;
            b2[tr] = min(min(b2[tr], o2), (u32)(mx >> 32));
        }
    }
    u64* tab1 = (u64*)(smem + SM_B);
    u32* tab2 = (u32*)(smem + SM_B + 2048);
    if ((l & 3) == 0) {
        #pragma unroll
        for (int tr = 0; tr < 4; tr++) {
            int row = wm * 32 + (tr >> 1) * 16 + (tr & 1) * 8 + (l >> 2);
            tab1[row * 2 + wn] = b1[tr];
            tab2[row * 2 + wn] = b2[tr];
        }
    }
    __syncthreads();
    if (tid < 128) {
        u64 p = tab1[tid * 2], q = tab1[tid * 2 + 1];
        u64 best = p < q ? p : q, worse = p < q ? q : p;
        u32 sec = min(min(tab2[tid * 2], tab2[tid * 2 + 1]), (u32)(worse >> 32));
        int n = m0 + tid;
        g_idx[n] = (int)(best & 0xFFFFFFFFull);
        float margin = fkeyinv(sec) - fkeyinv((u32)(best >> 32));
        if (!(margin > TAU)) { int pp = atomicAdd(&g_flag_cnt, 1); g_flag_tok[pp] = n; }
    }
}

// ---------------- rescue: exact fp32 argmin for flagged tokens ----------------
__global__ void __launch_bounds__(256) k_rescue(const float* __restrict__ x,
                                                const float* __restrict__ embed) {
    __shared__ float xs[256];
    __shared__ float bv[256]; __shared__ int bix[256];
    int tid = threadIdx.x;
    int cnt = *((volatile int*)&g_flag_cnt);
    for (int i = blockIdx.x; i < cnt; i += gridDim.x) {
        int n = g_flag_tok[i];
        int b = n >> 12, s = n & 4095;
        xs[tid] = x[(size_t)b * 1048576u + (size_t)tid * 4096u + s];
        __syncthreads();
        float best = 3.4e38f; int bi = 0;
        for (int cc = 0; cc < 4; cc++) {
            int code = tid * 4 + cc;
            const float4* e4 = (const float4*)(embed + code * 256);
            float acc = 0.f, e2 = 0.f;
            #pragma unroll 8
            for (int dq = 0; dq < 64; dq++) {
                float4 ev = e4[dq];
                acc = fmaf(ev.x, xs[dq*4+0], acc); e2 = fmaf(ev.x, ev.x, e2);
                acc = fmaf(ev.y, xs[dq*4+1], acc); e2 = fmaf(ev.y, ev.y, e2);
                acc = fmaf(ev.z, xs[dq*4+2], acc); e2 = fmaf(ev.z, ev.z, e2);
                acc = fmaf(ev.w, xs[dq*4+3], acc); e2 = fmaf(ev.w, ev.w, e2);
            }
            float sc = e2 - 2.f * acc;
            if (sc < best) { best = sc; bi = code; }
        }
        bv[tid] = best; bix[tid] = bi;
        __syncthreads();
        for (int o = 128; o; o >>= 1) {
            if (tid < o) {
                float v = bv[tid + o]; int ii = bix[tid + o];
                if (v < bv[tid] || (v == bv[tid] && ii < bix[tid])) { bv[tid] = v; bix[tid] = ii; }
            }
            __syncthreads();
        }
        if (tid == 0) g_idx[n] = bix[0];
        __syncthreads();
    }
}

// ---------------- fused quantized write + loss + dw scatter + idx out ----------------
__global__ void k_quant_dw(const float* __restrict__ x,
                           const float* __restrict__ embed,
                           float* __restrict__ qout, float* __restrict__ idxf_out)
{
    int d0 = blockIdx.x << 2;
    int n  = (blockIdx.y << 8) + threadIdx.x;
    int b = n >> 12, s = n & 4095;
    size_t base = (size_t)b * 1048576u + s;
    int k = g_idx[n];
    float4 q = *(const float4*)(embed + k * D_DIM + d0);
    if (blockIdx.x == 0) { idxf_out[n] = (float)k; atomicAdd(&g_batch_cs[k], 1.0f); }

    float x0 = x[base + (size_t)(d0 + 0) * 4096u];
    float x1 = x[base + (size_t)(d0 + 1) * 4096u];
    float x2 = x[base + (size_t)(d0 + 2) * 4096u];
    float x3 = x[base + (size_t)(d0 + 3) * 4096u];
    float t0 = q.x - x0, t1 = q.y - x1, t2 = q.z - x2, t3 = q.w - x3;
    qout[base + (size_t)(d0 + 0) * 4096u] = x0 + t0;
    qout[base + (size_t)(d0 + 1) * 4096u] = x1 + t1;
    qout[base + (size_t)(d0 + 2) * 4096u] = x2 + t2;
    qout[base + (size_t)(d0 + 3) * 4096u] = x3 + t3;
    float ls = t0*t0 + t1*t1 + t2*t2 + t3*t3;

    float* dst = g_dw + k * D_DIM + d0;
    asm volatile("red.global.add.v4.f32 [%0], {%1,%2,%3,%4};"
                 :: "l"(dst), "f"(x0), "f"(x1), "f"(x2), "f"(x3) : "memory");

    #pragma unroll
    for (int o = 16; o; o >>= 1) ls += __shfl_down_sync(0xffffffffu, ls, o);
    __shared__ float ws[8];
    int tid = threadIdx.x;
    if ((tid & 31) == 0) ws[tid >> 5] = ls;
    __syncthreads();
    if (tid == 0) {
        float sum = 0.f;
        #pragma unroll
        for (int i = 0; i < 8; i++) sum += ws[i];
        g_partials[blockIdx.y * 64 + blockIdx.x] = sum;
    }
}

// ---------------- finalize ----------------
__global__ void k_final(const float* __restrict__ cluster_size, float* __restrict__ loss_out) {
    __shared__ float sb[1024];
    int t = threadIdx.x;
    float s = 0.f;
    for (int i = t; i < 64 * 128; i += 1024) s += g_partials[i];
    sb[t] = s; __syncthreads();
    for (int o = 512; o; o >>= 1) { if (t < o) sb[t] += sb[t + o]; __syncthreads(); }
    if (t == 0) loss_out[0] = 0.25f * sb[0] / (float)Q_ELEMS;
    __syncthreads();
    float ncs = cluster_size[t] * 0.99f + 0.01f * g_batch_cs[t];
    sb[t] = ncs; __syncthreads();
    for (int o = 512; o; o >>= 1) { if (t < o) sb[t] += sb[t + o]; __syncthreads(); }
    float nsum = sb[0];
    g_cs[t] = nsum * (ncs + 1e-5f) / (nsum + 1024.0f * 1e-5f);
}

__global__ void k_newembed(const float* __restrict__ embed_avg, float* __restrict__ out) {
    int k = blockIdx.x, d = threadIdx.x;
    int o = k * D_DIM + d;
    out[o] = (embed_avg[o] * 0.99f + 0.01f * g_dw[o]) / g_cs[k];
}

// ---------------- launch ----------------
extern "C" void kernel_launch(void* const* d_in, const int* in_sizes, int n_in,
                              void* d_out, int out_size)
{
    const float* x         = (const float*)d_in[0];
    const float* embed     = (const float*)d_in[1];
    const float* embed_avg = (const float*)d_in[2];
    const float* cluster   = (const float*)d_in[3];

    float* out     = (float*)d_out;
    float* out_q   = out + 1;
    float* out_idx = out_q + Q_ELEMS;
    float* out_e   = out_idx + N_TOK;

    void *p_dw, *p_bc, *p_fc;
    cudaGetSymbolAddress(&p_dw, g_dw);
    cudaGetSymbolAddress(&p_bc, g_batch_cs);
    cudaGetSymbolAddress(&p_fc, g_flag_cnt);
    cudaMemsetAsync(p_dw, 0, sizeof(float) * K_CODES * D_DIM, 0);
    cudaMemsetAsync(p_bc, 0, sizeof(float) * K_CODES, 0);
    cudaMemsetAsync(p_fc, 0, sizeof(int), 0);

    cudaFuncSetAttribute(k_argmin, cudaFuncAttributeMaxDynamicSharedMemorySize, SM_TOTAL);

    k_esplit<<<K_CODES, D_DIM>>>(embed);
    k_argmin<<<256, 256, SM_TOTAL>>>(x);
    k_rescue<<<256, 256>>>(x, embed);
    dim3 g(64, 128);
    k_quant_dw<<<g, 256>>>(x, embed, out_q, out_idx);
    k_final<<<1, 1024>>>(cluster, out);
    k_newembed<<<K_CODES, D_DIM>>>(embed_avg, out_e);
}